// round 1
// baseline (speedup 1.0000x reference)
#include <cuda_runtime.h>
#include <math.h>

// Problem-size capacities (dataset: N=500000, E=8000000)
#define NMAX 500000
#define EMAX 8000000

#define CG_ITERS 20
#define TOL2 1e-8f   // CG_TOL^2, compare against ||r||^2

// ---- scratch (device globals; no allocation allowed) ----
__device__ float g_w[EMAX];                  // face weights  area/max(dist,1e-8)
__device__ float g_diag[NMAX];
__device__ float g_minv[NMAX];
__device__ float g_divacc[NMAX];             // flux accumulator
__device__ float g_phi[NMAX];
__device__ float g_r[NMAX];
__device__ float g_z[NMAX];
__device__ float g_p[NMAX];
__device__ float g_ap[NMAX];
__device__ float g_grad[3 * NMAX];
// scalars: 0=rz  1=rr  2=pAp_acc  3=rz_acc  4=rr_acc  5=beta  6=active flag
__device__ float g_sc[8];

// ---- block reduction: returns full sum in thread 0 of the block ----
__device__ __forceinline__ float blk_reduce(float v) {
    __shared__ float s[32];
    int lane = threadIdx.x & 31;
    int wp   = threadIdx.x >> 5;
    #pragma unroll
    for (int o = 16; o; o >>= 1) v += __shfl_down_sync(0xffffffffu, v, o);
    __syncthreads();                       // protect shared reuse across calls
    if (lane == 0) s[wp] = v;
    __syncthreads();
    float r = 0.f;
    int nw = blockDim.x >> 5;
    if (threadIdx.x < nw) r = s[threadIdx.x];
    if (wp == 0) {
        #pragma unroll
        for (int o = 16; o; o >>= 1) r += __shfl_down_sync(0xffffffffu, r, o);
    }
    return r;
}

// ---------------- setup ----------------

__global__ void k_zero(int n3) {   // n3 = 3*N
    int i = blockIdx.x * blockDim.x + threadIdx.x;
    if (i < n3) g_grad[i] = 0.f;
    if (i < (n3 / 3)) { g_diag[i] = 0.f; g_divacc[i] = 0.f; }
    if (i < 8) g_sc[i] = 0.f;
}

__global__ void k_edge_setup(const int* __restrict__ src,
                             const int* __restrict__ dst,
                             const float* __restrict__ u_hat,
                             const float* __restrict__ fn,
                             const float* __restrict__ fa,
                             const float* __restrict__ fd,
                             int E) {
    int e = blockIdx.x * blockDim.x + threadIdx.x;
    if (e >= E) return;
    int s = src[e], d = dst[e];
    float area = fa[e];
    float w = area / fmaxf(fd[e], 1e-8f);
    g_w[e] = w;
    atomicAdd(&g_diag[d], w);
    float n0 = fn[e * 3 + 0], n1 = fn[e * 3 + 1], n2 = fn[e * 3 + 2];
    float uf0 = 0.5f * (u_hat[s * 3 + 0] + u_hat[d * 3 + 0]);
    float uf1 = 0.5f * (u_hat[s * 3 + 1] + u_hat[d * 3 + 1]);
    float uf2 = 0.5f * (u_hat[s * 3 + 2] + u_hat[d * 3 + 2]);
    float flux = (uf0 * n0 + uf1 * n1 + uf2 * n2) * area;
    atomicAdd(&g_divacc[d], flux);
}

// phi0=0, r=b, z=minv*r, p=z, ap=diag*p; accumulate rz->sc0, rr->sc1, diag pAp part->sc2
__global__ void k_init_cg(const float* __restrict__ cv, int N) {
    int i = blockIdx.x * blockDim.x + threadIdx.x;
    float rz = 0.f, rr = 0.f, pap = 0.f;
    if (i < N) {
        float V = fmaxf(cv[i], 1e-12f);
        float b = g_divacc[i] / V;
        float d = g_diag[i];
        float mi = 1.f / fmaxf(d, 1e-8f);
        g_minv[i] = mi;
        g_phi[i] = 0.f;
        float r = b;
        float z = mi * r;
        g_r[i] = r; g_z[i] = z; g_p[i] = z;
        g_ap[i] = d * z;
        rz = r * z; rr = r * r; pap = d * z * z;
    }
    float t = blk_reduce(rz);
    if (threadIdx.x == 0) atomicAdd(&g_sc[0], t);
    t = blk_reduce(rr);
    if (threadIdx.x == 0) atomicAdd(&g_sc[1], t);
    t = blk_reduce(pap);
    if (threadIdx.x == 0) atomicAdd(&g_sc[2], t);
}

// ---------------- CG iteration ----------------

// ap[dst] += -w * p[src]; pAp += (-w*p[src]) * p[dst]
__global__ void k_edge_matvec(const int* __restrict__ src,
                              const int* __restrict__ dst, int E) {
    int e = blockIdx.x * blockDim.x + threadIdx.x;
    float contrib = 0.f;
    if (e < E) {
        int s = src[e], d = dst[e];
        float v = -g_w[e] * g_p[s];
        atomicAdd(&g_ap[d], v);
        contrib = v * g_p[d];
    }
    float t = blk_reduce(contrib);
    if (threadIdx.x == 0) atomicAdd(&g_sc[2], t);
}

// alpha = rz/(pAp+eps); if active: phi += a*p, r -= a*ap, z = minv*r; acc rz_new, rr_new
__global__ void k_update_phi_r(int N) {
    int i = blockIdx.x * blockDim.x + threadIdx.x;
    float rz = g_sc[0], rr = g_sc[1], pAp = g_sc[2];
    bool act = (rr >= TOL2);
    float alpha = rz / (pAp + 1e-12f);
    float rzc = 0.f, rrc = 0.f;
    if (i < N && act) {
        g_phi[i] += alpha * g_p[i];
        float rn = g_r[i] - alpha * g_ap[i];
        float zn = g_minv[i] * rn;
        g_r[i] = rn; g_z[i] = zn;
        rzc = rn * zn; rrc = rn * rn;
    }
    float t = blk_reduce(rzc);
    if (threadIdx.x == 0) atomicAdd(&g_sc[3], t);
    t = blk_reduce(rrc);
    if (threadIdx.x == 0) atomicAdd(&g_sc[4], t);
}

// single-thread scalar bookkeeping
__global__ void k_rotate() {
    float rr = g_sc[1];
    bool act = (rr >= TOL2);
    if (act) {
        g_sc[5] = g_sc[3] / (g_sc[0] + 1e-12f);  // beta
        g_sc[0] = g_sc[3];                       // rz <- rz_new
        g_sc[1] = g_sc[4];                       // rr <- rr_new
    } else {
        g_sc[5] = 0.f;
    }
    g_sc[6] = act ? 1.f : 0.f;
    g_sc[2] = 0.f; g_sc[3] = 0.f; g_sc[4] = 0.f; // zero accumulators for next iter
}

// if active: p = z + beta*p; always: ap = diag*p; acc pAp diag part
__global__ void k_update_p(int N) {
    int i = blockIdx.x * blockDim.x + threadIdx.x;
    bool act = (g_sc[6] != 0.f);
    float beta = g_sc[5];
    float pap = 0.f;
    if (i < N) {
        float p = g_p[i];
        if (act) { p = g_z[i] + beta * p; g_p[i] = p; }
        float d = g_diag[i];
        g_ap[i] = d * p;
        pap = d * p * p;
    }
    float t = blk_reduce(pap);
    if (threadIdx.x == 0) atomicAdd(&g_sc[2], t);
}

// ---------------- correction ----------------

__global__ void k_grad(const int* __restrict__ src,
                       const int* __restrict__ dst,
                       const float* __restrict__ fn, int E) {
    int e = blockIdx.x * blockDim.x + threadIdx.x;
    if (e >= E) return;
    int s = src[e], d = dst[e];
    float t = g_w[e] * g_phi[s];
    atomicAdd(&g_grad[d * 3 + 0], t * fn[e * 3 + 0]);
    atomicAdd(&g_grad[d * 3 + 1], t * fn[e * 3 + 1]);
    atomicAdd(&g_grad[d * 3 + 2], t * fn[e * 3 + 2]);
}

__global__ void k_final(const float* __restrict__ u_hat,
                        const float* __restrict__ cv,
                        float* __restrict__ out, int N) {
    int i = blockIdx.x * blockDim.x + threadIdx.x;
    if (i >= N) return;
    float Vi = 1.f / fmaxf(cv[i], 1e-12f);
    out[i * 3 + 0] = u_hat[i * 3 + 0] - g_grad[i * 3 + 0] * Vi;
    out[i * 3 + 1] = u_hat[i * 3 + 1] - g_grad[i * 3 + 1] * Vi;
    out[i * 3 + 2] = u_hat[i * 3 + 2] - g_grad[i * 3 + 2] * Vi;
    out[3 * N + i] = g_phi[i];
}

// ---------------- launch ----------------

extern "C" void kernel_launch(void* const* d_in, const int* in_sizes, int n_in,
                              void* d_out, int out_size) {
    const float* u_hat = (const float*)d_in[0];
    const int*   ei    = (const int*)  d_in[1];
    const float* fn    = (const float*)d_in[2];
    const float* fa    = (const float*)d_in[3];
    const float* fd    = (const float*)d_in[4];
    const float* cv    = (const float*)d_in[5];
    float* out = (float*)d_out;

    int N = in_sizes[5];          // cell_volumes
    int E = in_sizes[3];          // face_areas
    const int* src = ei;
    const int* dst = ei + E;

    const int B = 256;
    int gridE = (E + B - 1) / B;
    int gridN = (N + B - 1) / B;
    int grid3N = (3 * N + B - 1) / B;

    k_zero<<<grid3N, B>>>(3 * N);
    k_edge_setup<<<gridE, B>>>(src, dst, u_hat, fn, fa, fd, E);
    k_init_cg<<<gridN, B>>>(cv, N);

    for (int it = 0; it < CG_ITERS; ++it) {
        k_edge_matvec<<<gridE, B>>>(src, dst, E);
        k_update_phi_r<<<gridN, B>>>(N);
        k_rotate<<<1, 1>>>();
        k_update_p<<<gridN, B>>>(N);
    }

    k_grad<<<gridE, B>>>(src, dst, fn, E);
    k_final<<<gridN, B>>>(u_hat, cv, out, N);
}